// round 17
// baseline (speedup 1.0000x reference)
#include <cuda_runtime.h>
#include <cuda_fp16.h>
#include <cstdint>

// ---------------------------------------------------------------------------
// FishEyePatchEmbedding on GB300 (sm_103a) — fused persistent kernel:
// 296 CTAs (2/SM). Bids 0..147 = gather role (produce per-mTile A slices,
// publish flags), bids 148..295 = GEMM role (wprep, then claim tiles,
// spin on flags). Gather CTAs join the GEMM tile loop when done.
// GEMM body = measured-optimal R10 config (fp16 m16n8k16, 128x128, 3-stage).
// ---------------------------------------------------------------------------

#define PLANE   (736 * 736)
#define NBATCH  32
#define EMB     768
#define KDIM    768
#define OHN     23
#define OWN     48
#define SPP     (OHN * OWN)       // 1104
#define MTOT    (NBATCH * SPP)    // 35328

#define TILE_M  128
#define TILE_N  128
#define KCHUNK  64
#define KB      (KDIM / KCHUNK)   // 12
#define STAGES  3
#define LDSH    72

#define NSM     148
#define GRID    (2 * NSM)         // 296
#define MT      (MTOT / TILE_M)   // 276
#define NT      (EMB / TILE_N)    // 6
#define NTILES  (MT * NT)         // 1656
#define SLICE_E4 (TILE_M * KDIM / 4)   // 24576 e4 units per mTile slice

#define SA_HALFS   (TILE_M * LDSH)
#define SB_HALFS   (TILE_N * LDSH)
#define STG_HALFS  (SA_HALFS + SB_HALFS)
#define SMEM_HDR   64                       // claim slot etc.
#define SMEM_BIAS  (SMEM_HDR)               // 128 floats @ 64
#define SMEM_STG0  (SMEM_HDR + 512)
#define SMEM_TOTAL (SMEM_STG0 + STAGES * STG_HALFS * 2)   // 111168

__device__ __half g_A[(size_t)MTOT * KDIM];
__device__ __half g_W[(size_t)EMB * KDIM];
__device__ int    g_flag[MT];
__device__ int    g_tileCtr;
__device__ int    g_wprepCtr;

#define WPREP4   (EMB * KDIM / 4)           // 147456

// ---------------------------------------------------------------------------
__global__ void init_kernel() {
    int i = blockIdx.x * blockDim.x + threadIdx.x;
    if (i < MT) g_flag[i] = 0;
    if (i == MT)     g_tileCtr = 0;
    if (i == MT + 1) g_wprepCtr = 0;
}

// ---------------------------------------------------------------------------
__device__ __forceinline__ void cp16s(uint32_t sdst, const void* gsrc) {
    asm volatile("cp.async.cg.shared.global [%0], [%1], 16;" :: "r"(sdst), "l"(gsrc));
}
__device__ __forceinline__ void ldsm4(uint32_t& r0, uint32_t& r1,
                                      uint32_t& r2, uint32_t& r3, uint32_t a) {
    asm volatile("ldmatrix.sync.aligned.m8n8.x4.shared.b16 {%0,%1,%2,%3}, [%4];"
                 : "=r"(r0), "=r"(r1), "=r"(r2), "=r"(r3) : "r"(a));
}

// gather one mTile slice (all 256 threads), R10-proven per-element mapping
__device__ void gather_slice(int slice,
                             const float* __restrict__ x,
                             const int*   __restrict__ idx0,
                             const int*   __restrict__ idx1,
                             const float* __restrict__ w,
                             __half*      __restrict__ A,
                             int tid) {
    for (int u = tid; u < SLICE_E4; u += 256) {
        int e4 = slice * SLICE_E4 + u;
        int base = e4 * 4;
        int m = base / KDIM;
        int k = base - m * KDIM;

        int n  = m / SPP;
        int s  = m - n * SPP;
        int oh = s / OWN;
        int ow = s - oh * OWN;

        int c  = k >> 8;
        int r  = k & 255;
        int ky = r >> 4;
        int kx = r & 15;

        int t = (oh * 16 + ky) * 768 + ow * 16 + kx;

        const float* xp = x + (size_t)(n * 3 + c) * PLANE;

        int4   g0 = *reinterpret_cast<const int4*>(idx0 + t);
        int4   g1 = *reinterpret_cast<const int4*>(idx1 + t);
        float4 wt = *reinterpret_cast<const float4*>(w + t);

        float a0 = xp[g0.x], a1 = xp[g0.y], a2 = xp[g0.z], a3 = xp[g0.w];
        float b0 = xp[g1.x], b1 = xp[g1.y], b2 = xp[g1.z], b3 = xp[g1.w];

        float o0 = fmaf(b0 - a0, wt.x, a0);
        float o1 = fmaf(b1 - a1, wt.y, a1);
        float o2 = fmaf(b2 - a2, wt.z, a2);
        float o3 = fmaf(b3 - a3, wt.w, a3);

        __half2 h0 = __floats2half2_rn(o0, o1);
        __half2 h1 = __floats2half2_rn(o2, o3);
        uint2 st;
        st.x = *reinterpret_cast<uint32_t*>(&h0);
        st.y = *reinterpret_cast<uint32_t*>(&h1);
        *reinterpret_cast<uint2*>(A + base) = st;
    }
}

// ---------------------------------------------------------------------------
// Fused persistent kernel
// ---------------------------------------------------------------------------
__global__ void __launch_bounds__(256, 2)
fisheye_fused_kernel(const float* __restrict__ x,
                     const float* __restrict__ conv_w,
                     const float* __restrict__ bias,
                     const int*   __restrict__ idx0,
                     const int*   __restrict__ idx1,
                     const float* __restrict__ w,
                     float*       __restrict__ out) {
    extern __shared__ char smem[];
    int*    sclaim = reinterpret_cast<int*>(smem);
    float*  biass  = reinterpret_cast<float*>(smem + SMEM_BIAS);
    __half* stage0 = reinterpret_cast<__half*>(smem + SMEM_STG0);

    const int tid  = threadIdx.x;
    const int bid  = blockIdx.x;
    const int lane = tid & 31;
    const int warp = tid >> 5;

    __half* A  = g_A;
    __half* Wt = g_W;

    if (bid < NSM) {
        // ---------------- gather role ----------------
        // slice bid first (mTiles 0..147 all complete earliest), then bid+NSM
        gather_slice(bid, x, idx0, idx1, w, A, tid);
        __syncthreads();
        if (tid == 0) { __threadfence(); atomicExch(&g_flag[bid], 1); }
        int s2 = bid + NSM;
        if (s2 < MT) {
            gather_slice(s2, x, idx0, idx1, w, A, tid);
            __syncthreads();
            if (tid == 0) { __threadfence(); atomicExch(&g_flag[s2], 1); }
        }
    } else {
        // ---------------- wprep (GEMM role CTAs collectively) ----------------
        int i0 = (bid - NSM) * 256 + tid;
        for (int i = i0; i < WPREP4; i += NSM * 256) {
            float4 v = reinterpret_cast<const float4*>(conv_w)[i];
            __half2 h0 = __floats2half2_rn(v.x, v.y);
            __half2 h1 = __floats2half2_rn(v.z, v.w);
            uint2 st;
            st.x = *reinterpret_cast<uint32_t*>(&h0);
            st.y = *reinterpret_cast<uint32_t*>(&h1);
            *reinterpret_cast<uint2*>(Wt + i * 4) = st;
        }
        __syncthreads();
        if (tid == 0) { __threadfence(); atomicAdd(&g_wprepCtr, 1); }
    }

    // ---------------- wait for weights ready ----------------
    if (tid == 0) {
        while (atomicAdd(&g_wprepCtr, 0) < NSM) __nanosleep(200);
        __threadfence();
    }
    __syncthreads();

    // ---------------- persistent GEMM tile loop (all CTAs) ----------------
    const int wm  = (warp >> 2) * 64;
    const int wn  = (warp & 3) * 32;
    const int gId = lane >> 2;
    const int tig = lane & 3;

    const int laneRowA = (lane & 7) + ((lane >> 3) & 1) * 8;
    const int laneColA = (lane >> 4) * 8;
    const int laneRowB = (lane & 7) + (lane >> 4) * 8;
    const int laneColB = ((lane >> 3) & 1) * 8;

    while (true) {
        if (tid == 0) *sclaim = atomicAdd(&g_tileCtr, 1);
        __syncthreads();
        int t = *sclaim;
        if (t >= NTILES) break;
        int mTile = t / NT;
        int nTile = t - mTile * NT;

        if (tid == 0) {
            while (atomicAdd(&g_flag[mTile], 0) == 0) __nanosleep(200);
            __threadfence();
        }
        __syncthreads();

        if (tid < TILE_N) biass[tid] = bias[nTile * TILE_N + tid];

        const __half* Ag = A  + (size_t)mTile * TILE_M * KDIM;
        const __half* Bg = Wt + (size_t)nTile * TILE_N * KDIM;

        float acc[4][4][4];
        #pragma unroll
        for (int i = 0; i < 4; i++)
            #pragma unroll
            for (int j = 0; j < 4; j++)
                #pragma unroll
                for (int c = 0; c < 4; c++)
                    acc[i][j][c] = 0.0f;

        auto load_chunk = [&](int kb) {
            int s = kb % STAGES;
            __half* sA = stage0 + s * STG_HALFS;
            __half* sB = sA + SA_HALFS;
            const __half* ap = Ag + kb * KCHUNK;
            const __half* bp = Bg + kb * KCHUNK;
            #pragma unroll
            for (int i = 0; i < 4; i++) {
                int idx = tid + i * 256;
                int r = idx >> 3;
                int c8 = (idx & 7) * 8;
                cp16s((uint32_t)__cvta_generic_to_shared(sA + r * LDSH + c8),
                      ap + (size_t)r * KDIM + c8);
            }
            #pragma unroll
            for (int i = 0; i < 4; i++) {
                int idx = tid + i * 256;
                int r = idx >> 3;
                int c8 = (idx & 7) * 8;
                cp16s((uint32_t)__cvta_generic_to_shared(sB + r * LDSH + c8),
                      bp + (size_t)r * KDIM + c8);
            }
            asm volatile("cp.async.commit_group;");
        };

        load_chunk(0);
        load_chunk(1);

        for (int kb = 0; kb < KB; kb++) {
            if (kb < KB - 1) {
                asm volatile("cp.async.wait_group 1;");
            } else {
                asm volatile("cp.async.wait_group 0;");
            }
            __syncthreads();

            if (kb + 2 < KB) load_chunk(kb + 2);

            int s = kb % STAGES;
            const __half* sA = stage0 + s * STG_HALFS;
            const __half* sB = sA + SA_HALFS;
            uint32_t sAu = (uint32_t)__cvta_generic_to_shared(sA);
            uint32_t sBu = (uint32_t)__cvta_generic_to_shared(sB);

            #pragma unroll
            for (int ks = 0; ks < 4; ks++) {
                uint32_t af[4][4];
                uint32_t bf[2][4];
                #pragma unroll
                for (int mt = 0; mt < 4; mt++) {
                    uint32_t addr = sAu + 2 * ((wm + mt * 16 + laneRowA) * LDSH
                                               + ks * 16 + laneColA);
                    ldsm4(af[mt][0], af[mt][1], af[mt][2], af[mt][3], addr);
                }
                #pragma unroll
                for (int p = 0; p < 2; p++) {
                    uint32_t addr = sBu + 2 * ((wn + p * 16 + laneRowB) * LDSH
                                               + ks * 16 + laneColB);
                    ldsm4(bf[p][0], bf[p][1], bf[p][2], bf[p][3], addr);
                }
                #pragma unroll
                for (int mt = 0; mt < 4; mt++) {
                    #pragma unroll
                    for (int nt = 0; nt < 4; nt++) {
                        uint32_t b0 = bf[nt >> 1][(nt & 1) * 2 + 0];
                        uint32_t b1 = bf[nt >> 1][(nt & 1) * 2 + 1];
                        asm volatile(
                            "mma.sync.aligned.m16n8k16.row.col.f32.f16.f16.f32 "
                            "{%0,%1,%2,%3}, {%4,%5,%6,%7}, {%8,%9}, {%0,%1,%2,%3};"
                            : "+f"(acc[mt][nt][0]), "+f"(acc[mt][nt][1]),
                              "+f"(acc[mt][nt][2]), "+f"(acc[mt][nt][3])
                            : "r"(af[mt][0]), "r"(af[mt][1]),
                              "r"(af[mt][2]), "r"(af[mt][3]),
                              "r"(b0), "r"(b1));
                    }
                }
            }
        }

        // epilogue: bias + NCHW scatter
        #pragma unroll
        for (int mt = 0; mt < 4; mt++) {
            #pragma unroll
            for (int half = 0; half < 2; half++) {
                int m  = mTile * TILE_M + wm + mt * 16 + gId + half * 8;
                int nb = m / SPP;
                int sp = m - nb * SPP;
                float* ob = out + (size_t)nb * EMB * SPP + sp;
                #pragma unroll
                for (int nt = 0; nt < 4; nt++) {
                    int eloc = wn + nt * 8 + tig * 2;
                    int e0 = nTile * TILE_N + eloc;
                    float v0 = acc[mt][nt][half * 2 + 0] + biass[eloc];
                    float v1 = acc[mt][nt][half * 2 + 1] + biass[eloc + 1];
                    ob[(size_t)e0 * SPP]       = v0;
                    ob[(size_t)(e0 + 1) * SPP] = v1;
                }
            }
        }
        __syncthreads();   // biass/stages reuse safety before next claim
    }
}

// ---------------------------------------------------------------------------
// Launch
// ---------------------------------------------------------------------------
extern "C" void kernel_launch(void* const* d_in, const int* in_sizes, int n_in,
                              void* d_out, int out_size) {
    const float* x      = (const float*)d_in[0];
    const float* conv_w = (const float*)d_in[1];
    const float* conv_b = (const float*)d_in[2];
    const int*   idx0   = (const int*)d_in[3];
    const int*   idx1   = (const int*)d_in[4];
    const float* w      = (const float*)d_in[5];
    float* out = (float*)d_out;

    init_kernel<<<2, 256>>>();

    cudaFuncSetAttribute(fisheye_fused_kernel,
                         cudaFuncAttributeMaxDynamicSharedMemorySize,
                         SMEM_TOTAL);
    fisheye_fused_kernel<<<GRID, 256, SMEM_TOTAL>>>(
        x, conv_w, conv_b, idx0, idx1, w, out);
}